// round 16
// baseline (speedup 1.0000x reference)
#include <cuda_runtime.h>
#include <cuda_fp16.h>
#include <math.h>
#include <mma.h>

using namespace nvcuda;

#define Bb 32
#define Nn 200
#define Ss 192
#define Fin 8
#define Hh 64
#define Pp 48
#define FNn 4
#define Kk 10
#define NBb 3
#define BN (Bb*Nn)
#define SH (Ss*Hh)
#define KT (SH + Pp*Hh)   // 15360

#define XP 68     // padded float ldm for 64-wide tiles
#define WLH 200   // padded half ldm for full W rows
#define XPH 72    // padded half ldm for 64-wide half tiles
#define ALH 216   // padded half ldm for A rows (208 cols)
#define FH 72     // head: F half ldm (64-wide chunk)
#define WHH 56    // head: W half ldm (48-wide)

// scratch (allocation-free rule: __device__ globals; BSS zero-initialized)
__device__ float  g_X  [BN*SH];
__device__ __half g_Xhd[BN*SH];      // fp16 final-layer X (head input)
__device__ __half g_XWh[(BN+8)*SH];  // fp16 XW from tempgcn (+8 phantom rows, zero)
__device__ __half g_XFh[BN*Pp*Hh];   // fp16 future proj (head input)
__device__ __half g_HWh[KT*Pp];      // fp16 head_W
__device__ float  g_LA [Nn*Nn];
__device__ float  g_LB [Nn*Nn];
__device__ float  g_A  [Nn*Nn];
__device__ __half g_Ah [256*208];    // fp16 A, padded, zero outside [200][200]
__device__ float  g_D  [Nn];
__device__ float  g_HP [8*BN*Pp];    // head split-K partials

__device__ __forceinline__ float gelu_exact(float y) {
    return 0.5f*y*(1.f + erff(y*0.70710678118654752f));
}

__device__ __forceinline__ void cp16(void* dst, const void* src) {
    unsigned d = (unsigned)__cvta_generic_to_shared(dst);
    asm volatile("cp.async.cg.shared.global [%0], [%1], 16;\n" :: "r"(d), "l"(src));
}
__device__ __forceinline__ void cp_commit() {
    asm volatile("cp.async.commit_group;\n");
}
template<int N>
__device__ __forceinline__ void cp_wait() {
    asm volatile("cp.async.wait_group %0;\n" :: "n"(N));
}

// ---------------- kernel 1: instance norm + proj + node_emb ------------------------
__global__ __launch_bounds__(256) void k_innorm_proj(
    const float* __restrict__ x, const float* __restrict__ in_w, const float* __restrict__ in_b,
    const float* __restrict__ pw, const float* __restrict__ pb, const float* __restrict__ emb)
{
    __shared__ float xs[Ss*Fin];
    __shared__ float pws[Fin*Hh];
    __shared__ float mu[Fin], ri[Fin];
    int bn = blockIdx.x;
    int tid = threadIdx.x;
    int wid = tid >> 5, lane = tid & 31;
    const float* xin = x + (size_t)bn*Ss*Fin;
    for (int i = tid; i < Ss*Fin; i += 256) xs[i] = xin[i];
    for (int i = tid; i < Fin*Hh; i += 256) pws[i] = pw[i];
    __syncthreads();
    {
        float s = 0.f, q = 0.f;
        #pragma unroll
        for (int r = 0; r < 6; r++) {
            float v = xs[(lane + 32*r)*Fin + wid];
            s += v; q += v*v;
        }
        #pragma unroll
        for (int o = 16; o > 0; o >>= 1) {
            s += __shfl_xor_sync(0xffffffffu, s, o);
            q += __shfl_xor_sync(0xffffffffu, q, o);
        }
        if (lane == 0) {
            float m = s * (1.f/Ss);
            float var = q * (1.f/Ss) - m*m;
            mu[wid] = m; ri[wid] = rsqrtf(var + 1e-5f);
        }
    }
    __syncthreads();
    for (int i = tid; i < Ss*Fin; i += 256) {
        int f = i & (Fin-1);
        xs[i] = (xs[i]-mu[f])*ri[f]*in_w[f] + in_b[f];
    }
    __syncthreads();
    int h = tid & 63, sb = tid >> 6;
    int n = bn % Nn;
    float bias = pb[h] + emb[n*Hh + h];
    float* xo = g_X + (size_t)bn*SH;
    for (int s = sb; s < Ss; s += 4) {
        float acc = bias;
        #pragma unroll
        for (int f = 0; f < Fin; f++) acc += xs[s*Fin+f]*pws[f*Hh+h];
        xo[s*Hh+h] = acc;
    }
}

// ---------------- kernel 2: adjacency + norm + fp16 conversion (1 block) -----------
__global__ __launch_bounds__(256) void k_adj(
    const float* __restrict__ adj, const float* __restrict__ emb, const float* __restrict__ ga)
{
    int tid = threadIdx.x;
    for (int e = tid; e < Nn*Nn; e += 256) {
        int i = e / Nn, j = e % Nn;
        float acc = 0.f;
        for (int k = 0; k < Hh; k++) acc += emb[i*Hh+k]*emb[j*Hh+k];
        float v = fmaxf(acc, 0.f);
        g_LA[e] = v; g_LB[e] = v;
    }
    __syncthreads();
    float alpha = ga[0];
    if (tid < Nn) {
        int r = tid;
        const float* la = g_LA + r*Nn;
        float* lb = g_LB + r*Nn;
        int   idxs[Kk];
        float vals[Kk];
        for (int k = 0; k < Kk; k++) {
            float bv = -1e30f; int bi = 0;
            for (int j = 0; j < Nn; j++) { float v = lb[j]; if (v > bv) { bv = v; bi = j; } }
            idxs[k] = bi; vals[k] = la[bi]; lb[bi] = -1e30f;
        }
        float mx = 0.f;
        for (int k = 0; k < Kk; k++) mx = fmaxf(mx, vals[k]);
        float base = expf(0.f - mx);
        float ev[Kk]; float cs = 0.f;
        for (int k = 0; k < Kk; k++) { ev[k] = expf(vals[k]-mx); cs += ev[k]; }
        float inv = 1.f / ((float)(Nn-Kk)*base + cs);
        float* arow = g_A + r*Nn;
        float bsm = base*inv;
        for (int j = 0; j < Nn; j++) arow[j] = bsm;
        for (int k = 0; k < Kk; k++) arow[idxs[k]] = ev[k]*inv;
        float rs = 0.f;
        for (int j = 0; j < Nn; j++) {
            float c = alpha*adj[r*Nn+j] + (1.f-alpha)*arow[j];
            if (j == r) c = 1.f;
            arow[j] = c; rs += c;
        }
        g_D[r] = rsqrtf(fmaxf(rs, 1.f));
    }
    __syncthreads();
    for (int e = tid; e < Nn*Nn; e += 256) {
        int i = e / Nn, j = e % Nn;
        g_A[e] *= g_D[i]*g_D[j];
    }
    __syncthreads();
    for (int idx = tid; idx < 256*208; idx += 256) {
        int r = idx / 208, cc = idx % 208;
        float v = (r < Nn && cc < Nn) ? g_A[r*Nn + cc] : 0.f;
        g_Ah[idx] = __float2half_rn(v);
    }
}

// ---------------- kernel: pre-round head_W to fp16 ---------------------------------
__global__ __launch_bounds__(256) void k_hwt(const float* __restrict__ hw)
{
    int idx = blockIdx.x*256 + threadIdx.x;
    if (idx < KT*Pp) g_HWh[idx] = __float2half_rn(hw[idx]);
}

// ---------------- persistent fused temporal MLP + gcn_W (fp16 wmma, 512 thr) -------
#define TG_SMEM ((Ss*WLH + Ss*XPH + Hh*XPH)*2 + (Ss*XP + Ss)*4)
__global__ __launch_bounds__(512) void k_tempgcn_mma(
    const float* __restrict__ W, const float* __restrict__ tb, const float* __restrict__ Wg)
{
    extern __shared__ char smc[];
    __half* WsmH = (__half*)smc;             // [192][WLH]
    __half* XsH  = WsmH + Ss*WLH;            // [192][XPH]
    __half* WgsH = XsH + Ss*XPH;             // [64][XPH]
    float*  Ys   = (float*)(WgsH + Hh*XPH);  // [192][XP]
    float*  tbs  = Ys + Ss*XP;               // [192]

    int tid = threadIdx.x;
    int wid = tid >> 5;
    int wt = wid >> 2;
    int wh = wid & 3;

    for (int i4 = tid; i4 < Ss*48; i4 += 512) {
        int t = i4 / 48, c4 = i4 % 48;
        float4 v = *(const float4*)(W + (size_t)t*Ss + c4*4);
        __half2* d = (__half2*)(WsmH + t*WLH + c4*4);
        d[0] = __floats2half2_rn(v.x, v.y);
        d[1] = __floats2half2_rn(v.z, v.w);
    }
    #pragma unroll
    for (int q = 0; q < 2; q++) {
        int i4 = tid + 512*q;
        int r = i4 >> 4, c4 = i4 & 15;
        float4 v = *(const float4*)(Wg + (size_t)r*Hh + c4*4);
        __half2* d = (__half2*)(WgsH + r*XPH + c4*4);
        d[0] = __floats2half2_rn(v.x, v.y);
        d[1] = __floats2half2_rn(v.z, v.w);
    }
    if (tid < Ss) tbs[tid] = tb[tid];

    for (int bn = blockIdx.x; bn < BN; bn += gridDim.x) {
        float* xg = g_X + (size_t)bn*SH;

        #pragma unroll
        for (int q = 0; q < 6; q++) {
            int i4 = tid + 512*q;
            int t = i4 >> 4, c4 = i4 & 15;
            float4 v = *(const float4*)(xg + (size_t)t*Hh + c4*4);
            __half2* d = (__half2*)(XsH + t*XPH + c4*4);
            d[0] = __floats2half2_rn(v.x, v.y);
            d[1] = __floats2half2_rn(v.z, v.w);
        }
        __syncthreads();

        wmma::fragment<wmma::accumulator,16,16,16,float> c[3];
        #pragma unroll
        for (int i = 0; i < 3; i++) wmma::fill_fragment(c[i], 0.f);

        #pragma unroll 4
        for (int k16 = 0; k16 < 12; k16++) {
            wmma::fragment<wmma::matrix_a,16,16,16,__half,wmma::row_major> a[3];
            wmma::fragment<wmma::matrix_b,16,16,16,__half,wmma::row_major> bf;
            #pragma unroll
            for (int i = 0; i < 3; i++)
                wmma::load_matrix_sync(a[i], WsmH + (wt*48 + i*16)*WLH + k16*16, WLH);
            wmma::load_matrix_sync(bf, XsH + k16*16*XPH + wh*16, XPH);
            #pragma unroll
            for (int i = 0; i < 3; i++)
                wmma::mma_sync(c[i], a[i], bf, c[i]);
        }
        __syncthreads();

        #pragma unroll
        for (int i = 0; i < 3; i++)
            wmma::store_matrix_sync(Ys + (wt*48 + i*16)*XP + wh*16,
                                    c[i], XP, wmma::mem_row_major);
        __syncthreads();

        #pragma unroll 8
        for (int q = 0; q < 24; q++) {
            int i = tid + 512*q;
            int t = i >> 6, h = i & 63;
            float y = Ys[t*XP + h] + tbs[t];
            float xn = xg[i] + gelu_exact(y);
            xg[i] = xn;
            XsH[t*XPH + h] = __float2half_rn(xn);
        }
        __syncthreads();

        // GEMM2: XW = x_new @ Wg (fp16) -> g_XWh
        #pragma unroll
        for (int i = 0; i < 3; i++) wmma::fill_fragment(c[i], 0.f);
        #pragma unroll
        for (int k16 = 0; k16 < 4; k16++) {
            wmma::fragment<wmma::matrix_a,16,16,16,__half,wmma::row_major> a[3];
            wmma::fragment<wmma::matrix_b,16,16,16,__half,wmma::row_major> bf;
            #pragma unroll
            for (int i = 0; i < 3; i++)
                wmma::load_matrix_sync(a[i], XsH + (wt*48 + i*16)*XPH + k16*16, XPH);
            wmma::load_matrix_sync(bf, WgsH + k16*16*XPH + wh*16, XPH);
            #pragma unroll
            for (int i = 0; i < 3; i++)
                wmma::mma_sync(c[i], a[i], bf, c[i]);
        }
        #pragma unroll
        for (int i = 0; i < 3; i++)
            wmma::store_matrix_sync(Ys + (wt*48 + i*16)*XP + wh*16,
                                    c[i], XP, wmma::mem_row_major);
        __syncthreads();
        __half* xwo = g_XWh + (size_t)bn*SH;
        #pragma unroll 4
        for (int q = 0; q < 12; q++) {
            int i = tid + 512*q;
            int t = i >> 5, hp = i & 31;
            float2 v = *(const float2*)(Ys + t*XP + hp*2);
            *(__half2*)(xwo + t*Hh + hp*2) = __floats2half2_rn(v.x, v.y);
        }
        __syncthreads();
    }
}

// ---------------- mixln fp16: A staged once, 4 s-blocks per CTA --------------------
#define MM 128
#define SBT 4
#define ML_SMEM (MM*ALH*2 + MM*XP*4)
__global__ __launch_bounds__(256, 2) void k_mixln_mma(
    const float* __restrict__ gb, const float* __restrict__ lw, const float* __restrict__ lb,
    int last)
{
    extern __shared__ char smc[];
    __half* AsH = (__half*)smc;                 // [128][ALH]
    __half* BsH = (__half*)(smc + MM*ALH*2);    // [208][XPH] (union with Out)
    float*  Out = (float*) (smc + MM*ALH*2);    // [128][XP]

    int b = blockIdx.z, m0 = blockIdx.y*MM, sblk0 = blockIdx.x*SBT;
    int tid = threadIdx.x, wid = tid >> 5, lane = tid & 31;
    int wm = wid >> 1, whh = wid & 1;

    int wmax = (blockIdx.y == 0) ? 4 : 3;
    int rowcnt = wmax * 32;
    bool act = (wm < wmax);

    // stage A-slice once
    for (int i = tid; i < rowcnt*26; i += 256) {
        int row = i / 26, c8 = i % 26;
        cp16(AsH + row*ALH + c8*8, g_Ah + (size_t)(m0+row)*208 + c8*8);
    }
    cp_commit();

    float gb0 = gb[lane],    gb1 = gb[lane+32];
    float lw0 = lw[lane],    lw1 = lw[lane+32];
    float lb0 = lb[lane],    lb1 = lb[lane+32];

    for (int ss = 0; ss < SBT; ss++) {
        int sblk = sblk0 + ss;
        const __half* xwb = g_XWh + (size_t)b*Nn*SH + (size_t)sblk*Hh;

        // stage B [208][64]
        for (int i = tid; i < 208*8; i += 256) {
            int n = i >> 3, c8 = i & 7;
            cp16(BsH + n*XPH + c8*8, xwb + (size_t)n*SH + c8*8);
        }
        cp_commit();
        cp_wait<0>();
        __syncthreads();

        wmma::fragment<wmma::accumulator,16,16,16,float> c[2][2];
        #pragma unroll
        for (int i = 0; i < 2; i++)
            #pragma unroll
            for (int j = 0; j < 2; j++) wmma::fill_fragment(c[i][j], 0.f);

        if (act) {
            #pragma unroll 1
            for (int k16 = 0; k16 < 13; k16++) {
                wmma::fragment<wmma::matrix_a,16,16,16,__half,wmma::row_major> a[2];
                wmma::fragment<wmma::matrix_b,16,16,16,__half,wmma::row_major> bf[2];
                #pragma unroll
                for (int i = 0; i < 2; i++)
                    wmma::load_matrix_sync(a[i], AsH + (wm*32 + i*16)*ALH + k16*16, ALH);
                #pragma unroll
                for (int j = 0; j < 2; j++)
                    wmma::load_matrix_sync(bf[j], BsH + k16*16*XPH + whh*32 + j*16, XPH);
                #pragma unroll
                for (int i = 0; i < 2; i++)
                    #pragma unroll
                    for (int j = 0; j < 2; j++)
                        wmma::mma_sync(c[i][j], a[i], bf[j], c[i][j]);
            }
        }
        __syncthreads();   // BsH reads done; Out overwrites union

        if (act) {
            #pragma unroll
            for (int i = 0; i < 2; i++)
                #pragma unroll
                for (int j = 0; j < 2; j++)
                    wmma::store_matrix_sync(Out + (wm*32 + i*16)*XP + whh*32 + j*16,
                                            c[i][j], XP, wmma::mem_row_major);
        }
        __syncthreads();

        #pragma unroll
        for (int it = 0; it < 16; it++) {
            int r = wid*16 + it;
            int m = m0 + r;
            if (m >= Nn) break;
            size_t xi = ((size_t)(b*Nn + m)*Ss + sblk)*Hh + lane;
            float v0 = g_X[xi]      + Out[r*XP + lane]      + gb0;
            float v1 = g_X[xi + 32] + Out[r*XP + lane + 32] + gb1;
            float s = v0 + v1, q = v0*v0 + v1*v1;
            #pragma unroll
            for (int o = 16; o > 0; o >>= 1) {
                s += __shfl_xor_sync(0xffffffffu, s, o);
                q += __shfl_xor_sync(0xffffffffu, q, o);
            }
            float mu = s*(1.f/Hh), var = q*(1.f/Hh) - mu*mu;
            float rinv = rsqrtf(var + 1e-5f);
            float o0 = (v0-mu)*rinv*lw0 + lb0;
            float o1 = (v1-mu)*rinv*lw1 + lb1;
            g_X[xi]      = o0;
            g_X[xi + 32] = o1;
            if (last) {
                g_Xhd[xi]      = __float2half_rn(o0);
                g_Xhd[xi + 32] = __float2half_rn(o1);
            }
        }
        __syncthreads();   // LN reads of Out done before next B overwrites
    }
}

// ---------------- kernel: future projection (fp16 output) --------------------------
__global__ __launch_bounds__(256) void k_futr(
    const float* __restrict__ xf, const float* __restrict__ fw, const float* __restrict__ fb)
{
    int idx = blockIdx.x*blockDim.x + threadIdx.x;
    const int tot = BN*Pp*Hh;
    if (idx >= tot) return;
    int h = idx & 63;
    int p = (idx >> 6) % Pp;
    int bn = idx / (Pp*Hh);
    const float* xr = xf + ((size_t)bn*Pp + p)*FNn;
    float acc = fb[h];
    #pragma unroll
    for (int f = 0; f < FNn; f++) acc += xr[f]*fw[f*Hh+h];
    g_XFh[idx] = __float2half_rn(acc);
}

// ---------------- head GEMM, fp16 wmma split-K, cp.async double-buffer -------------
#define HD_SMEM ((128*FH + 64*WHH)*2*2)
__global__ __launch_bounds__(256) void k_head_mma()
{
    extern __shared__ char smhc[];
    __half* F0 = (__half*)smhc;
    __half* W0 = F0 + 128*FH;
    __half* F1 = W0 + 64*WHH;
    __half* W1 = F1 + 128*FH;

    int m0 = blockIdx.x*128;
    int k0 = blockIdx.y*(KT/8);      // 1920 per split, 30 chunks of 64
    int tid = threadIdx.x, wid = tid >> 5;

    wmma::fragment<wmma::accumulator,16,16,16,float> c[3];
    #pragma unroll
    for (int j = 0; j < 3; j++) wmma::fill_fragment(c[j], 0.f);

    {
        int kc = k0;
        #pragma unroll
        for (int q = 0; q < 4; q++) {
            int i8 = tid + 256*q;
            int row = i8 >> 3, cc = i8 & 7;
            int k = kc + cc*8;
            const __half* src = (k < SH) ? (g_Xhd + (size_t)(m0+row)*SH + k)
                                         : (g_XFh + (size_t)(m0+row)*(Pp*Hh) + (k - SH));
            cp16(F0 + row*FH + cc*8, src);
        }
        for (int i8 = tid; i8 < 64*6; i8 += 256) {
            int row = i8 / 6, cc = i8 % 6;
            cp16(W0 + row*WHH + cc*8, g_HWh + (size_t)(kc+row)*Pp + cc*8);
        }
        cp_commit();
    }

    for (int ch = 0; ch < 30; ch++) {
        __half* Fb = (ch & 1) ? F1 : F0;
        __half* Wb = (ch & 1) ? W1 : W0;
        if (ch < 29) {
            int kc = k0 + (ch+1)*64;
            __half* Fn = ((ch+1) & 1) ? F1 : F0;
            __half* Wn = ((ch+1) & 1) ? W1 : W0;
            #pragma unroll
            for (int q = 0; q < 4; q++) {
                int i8 = tid + 256*q;
                int row = i8 >> 3, cc = i8 & 7;
                int k = kc + cc*8;
                const __half* src = (k < SH) ? (g_Xhd + (size_t)(m0+row)*SH + k)
                                             : (g_XFh + (size_t)(m0+row)*(Pp*Hh) + (k - SH));
                cp16(Fn + row*FH + cc*8, src);
            }
            for (int i8 = tid; i8 < 64*6; i8 += 256) {
                int row = i8 / 6, cc = i8 % 6;
                cp16(Wn + row*WHH + cc*8, g_HWh + (size_t)(kc+row)*Pp + cc*8);
            }
            cp_commit();
            cp_wait<1>();
        } else {
            cp_wait<0>();
        }
        __syncthreads();

        #pragma unroll
        for (int k16 = 0; k16 < 4; k16++) {
            wmma::fragment<wmma::matrix_a,16,16,16,__half,wmma::row_major> a;
            wmma::load_matrix_sync(a, Fb + wid*16*FH + k16*16, FH);
            #pragma unroll
            for (int j = 0; j < 3; j++) {
                wmma::fragment<wmma::matrix_b,16,16,16,__half,wmma::row_major> bf;
                wmma::load_matrix_sync(bf, Wb + k16*16*WHH + j*16, WHH);
                wmma::mma_sync(c[j], a, bf, c[j]);
            }
        }
        __syncthreads();
    }
    float* hp = g_HP + (size_t)blockIdx.y*BN*Pp + (size_t)(m0 + wid*16)*Pp;
    #pragma unroll
    for (int j = 0; j < 3; j++)
        wmma::store_matrix_sync(hp + j*16, c[j], Pp, wmma::mem_row_major);
}

__global__ __launch_bounds__(256) void k_head_red(
    const float* __restrict__ hb, float* __restrict__ out)
{
    int idx = blockIdx.x*256 + threadIdx.x;
    if (idx >= BN*Pp) return;
    int p = idx % Pp;
    float acc = hb[p];
    #pragma unroll
    for (int z = 0; z < 8; z++) acc += g_HP[(size_t)z*BN*Pp + idx];
    out[idx] = acc;
}

// ---------------- launcher ---------------------------------------------------------
extern "C" void kernel_launch(void* const* d_in, const int* in_sizes, int n_in,
                              void* d_out, int out_size)
{
    const float* x        = (const float*)d_in[0];
    const float* x_future = (const float*)d_in[1];
    const float* adj      = (const float*)d_in[2];
    const float* node_emb = (const float*)d_in[3];
    const float* galpha   = (const float*)d_in[4];
    const float* in_w     = (const float*)d_in[5];
    const float* in_b     = (const float*)d_in[6];
    const float* proj_W   = (const float*)d_in[7];
    const float* proj_b   = (const float*)d_in[8];
    const float* temp_W   = (const float*)d_in[9];
    const float* temp_b   = (const float*)d_in[10];
    const float* gcn_W    = (const float*)d_in[11];
    const float* gcn_b    = (const float*)d_in[12];
    const float* ln_w     = (const float*)d_in[13];
    const float* ln_b     = (const float*)d_in[14];
    const float* futr_W   = (const float*)d_in[15];
    const float* futr_b   = (const float*)d_in[16];
    const float* head_W   = (const float*)d_in[17];
    const float* head_b   = (const float*)d_in[18];
    float* out = (float*)d_out;

    static bool attr_set = false;
    if (!attr_set) {
        cudaFuncSetAttribute(k_tempgcn_mma, cudaFuncAttributeMaxDynamicSharedMemorySize, TG_SMEM);
        cudaFuncSetAttribute(k_mixln_mma,   cudaFuncAttributeMaxDynamicSharedMemorySize, ML_SMEM);
        cudaFuncSetAttribute(k_head_mma,    cudaFuncAttributeMaxDynamicSharedMemorySize, HD_SMEM);
        attr_set = true;
    }

    // launch order: my #4 = first mixln (profiled by ncu)
    k_innorm_proj<<<BN, 256>>>(x, in_w, in_b, proj_W, proj_b, node_emb);      // 1
    k_adj<<<1, 256>>>(adj, node_emb, galpha);                                  // 2
    for (int i = 0; i < NBb; i++) {
        k_tempgcn_mma<<<148, 512, TG_SMEM>>>(temp_W + (size_t)i*Ss*Ss,         // 3,5,7
                                             temp_b + (size_t)i*Ss,
                                             gcn_W + (size_t)i*Hh*Hh);
        k_mixln_mma<<<dim3(Ss/SBT, 2, Bb), 256, ML_SMEM>>>(gcn_b + (size_t)i*Hh, // 4 <- profiled
                                                           ln_w + (size_t)i*Hh,
                                                           ln_b + (size_t)i*Hh,
                                                           (i == NBb-1) ? 1 : 0);
    }
    {
        const int tot = BN*Pp*Hh;
        k_futr<<<(tot + 255)/256, 256>>>(x_future, futr_W, futr_b);
    }
    k_hwt<<<(KT*Pp + 255)/256, 256>>>(head_W);
    k_head_mma<<<dim3(50, 8), 256, HD_SMEM>>>();
    k_head_red<<<(BN*Pp + 255)/256, 256>>>(head_b, out);
}

// round 17
// speedup vs baseline: 1.0799x; 1.0799x over previous
#include <cuda_runtime.h>
#include <cuda_fp16.h>
#include <math.h>
#include <mma.h>

using namespace nvcuda;

#define Bb 32
#define Nn 200
#define Ss 192
#define Fin 8
#define Hh 64
#define Pp 48
#define FNn 4
#define Kk 10
#define NBb 3
#define BN (Bb*Nn)
#define SH (Ss*Hh)
#define KT (SH + Pp*Hh)   // 15360

#define XP 68     // padded float ldm for 64-wide tiles
#define WLH 200   // padded half ldm for full W rows
#define XPH 72    // padded half ldm for 64-wide half tiles
#define ALH 216   // padded half ldm for A rows (208 cols)
#define FH 72     // head: F half ldm (64-wide chunk)
#define WHH 56    // head: W half ldm (48-wide)

// scratch (allocation-free rule: __device__ globals; BSS zero-initialized)
__device__ float  g_X  [BN*SH];
__device__ __half g_Xhd[BN*SH];      // fp16 final-layer X (head input)
__device__ __half g_XWh[(BN+8)*SH];  // fp16 XW from tempgcn (+8 phantom rows, zero)
__device__ __half g_XFh[BN*Pp*Hh];   // fp16 future proj (head input)
__device__ __half g_HWh[KT*Pp];      // fp16 head_W
__device__ float  g_LA [Nn*Nn];
__device__ float  g_LB [Nn*Nn];
__device__ float  g_A  [Nn*Nn];
__device__ __half g_Ah [256*208];    // fp16 A, padded, zero outside [200][200]
__device__ float  g_D  [Nn];
__device__ float  g_HP [8*BN*Pp];    // head split-K partials

__device__ __forceinline__ float gelu_exact(float y) {
    return 0.5f*y*(1.f + erff(y*0.70710678118654752f));
}

__device__ __forceinline__ void cp16(void* dst, const void* src) {
    unsigned d = (unsigned)__cvta_generic_to_shared(dst);
    asm volatile("cp.async.cg.shared.global [%0], [%1], 16;\n" :: "r"(d), "l"(src));
}
__device__ __forceinline__ void cp_commit() {
    asm volatile("cp.async.commit_group;\n");
}
template<int N>
__device__ __forceinline__ void cp_wait() {
    asm volatile("cp.async.wait_group %0;\n" :: "n"(N));
}

// ---------------- kernel 1: instance norm + proj + node_emb ------------------------
__global__ __launch_bounds__(256) void k_innorm_proj(
    const float* __restrict__ x, const float* __restrict__ in_w, const float* __restrict__ in_b,
    const float* __restrict__ pw, const float* __restrict__ pb, const float* __restrict__ emb)
{
    __shared__ float xs[Ss*Fin];
    __shared__ float pws[Fin*Hh];
    __shared__ float mu[Fin], ri[Fin];
    int bn = blockIdx.x;
    int tid = threadIdx.x;
    int wid = tid >> 5, lane = tid & 31;
    const float* xin = x + (size_t)bn*Ss*Fin;
    for (int i = tid; i < Ss*Fin; i += 256) xs[i] = xin[i];
    for (int i = tid; i < Fin*Hh; i += 256) pws[i] = pw[i];
    __syncthreads();
    {
        float s = 0.f, q = 0.f;
        #pragma unroll
        for (int r = 0; r < 6; r++) {
            float v = xs[(lane + 32*r)*Fin + wid];
            s += v; q += v*v;
        }
        #pragma unroll
        for (int o = 16; o > 0; o >>= 1) {
            s += __shfl_xor_sync(0xffffffffu, s, o);
            q += __shfl_xor_sync(0xffffffffu, q, o);
        }
        if (lane == 0) {
            float m = s * (1.f/Ss);
            float var = q * (1.f/Ss) - m*m;
            mu[wid] = m; ri[wid] = rsqrtf(var + 1e-5f);
        }
    }
    __syncthreads();
    for (int i = tid; i < Ss*Fin; i += 256) {
        int f = i & (Fin-1);
        xs[i] = (xs[i]-mu[f])*ri[f]*in_w[f] + in_b[f];
    }
    __syncthreads();
    int h = tid & 63, sb = tid >> 6;
    int n = bn % Nn;
    float bias = pb[h] + emb[n*Hh + h];
    float* xo = g_X + (size_t)bn*SH;
    for (int s = sb; s < Ss; s += 4) {
        float acc = bias;
        #pragma unroll
        for (int f = 0; f < Fin; f++) acc += xs[s*Fin+f]*pws[f*Hh+h];
        xo[s*Hh+h] = acc;
    }
}

// ---------------- kernel 2: adjacency + norm + fp16 conversion (1 block) -----------
__global__ __launch_bounds__(256) void k_adj(
    const float* __restrict__ adj, const float* __restrict__ emb, const float* __restrict__ ga)
{
    int tid = threadIdx.x;
    for (int e = tid; e < Nn*Nn; e += 256) {
        int i = e / Nn, j = e % Nn;
        float acc = 0.f;
        for (int k = 0; k < Hh; k++) acc += emb[i*Hh+k]*emb[j*Hh+k];
        float v = fmaxf(acc, 0.f);
        g_LA[e] = v; g_LB[e] = v;
    }
    __syncthreads();
    float alpha = ga[0];
    if (tid < Nn) {
        int r = tid;
        const float* la = g_LA + r*Nn;
        float* lb = g_LB + r*Nn;
        int   idxs[Kk];
        float vals[Kk];
        for (int k = 0; k < Kk; k++) {
            float bv = -1e30f; int bi = 0;
            for (int j = 0; j < Nn; j++) { float v = lb[j]; if (v > bv) { bv = v; bi = j; } }
            idxs[k] = bi; vals[k] = la[bi]; lb[bi] = -1e30f;
        }
        float mx = 0.f;
        for (int k = 0; k < Kk; k++) mx = fmaxf(mx, vals[k]);
        float base = expf(0.f - mx);
        float ev[Kk]; float cs = 0.f;
        for (int k = 0; k < Kk; k++) { ev[k] = expf(vals[k]-mx); cs += ev[k]; }
        float inv = 1.f / ((float)(Nn-Kk)*base + cs);
        float* arow = g_A + r*Nn;
        float bsm = base*inv;
        for (int j = 0; j < Nn; j++) arow[j] = bsm;
        for (int k = 0; k < Kk; k++) arow[idxs[k]] = ev[k]*inv;
        float rs = 0.f;
        for (int j = 0; j < Nn; j++) {
            float c = alpha*adj[r*Nn+j] + (1.f-alpha)*arow[j];
            if (j == r) c = 1.f;
            arow[j] = c; rs += c;
        }
        g_D[r] = rsqrtf(fmaxf(rs, 1.f));
    }
    __syncthreads();
    for (int e = tid; e < Nn*Nn; e += 256) {
        int i = e / Nn, j = e % Nn;
        g_A[e] *= g_D[i]*g_D[j];
    }
    __syncthreads();
    for (int idx = tid; idx < 256*208; idx += 256) {
        int r = idx / 208, cc = idx % 208;
        float v = (r < Nn && cc < Nn) ? g_A[r*Nn + cc] : 0.f;
        g_Ah[idx] = __float2half_rn(v);
    }
}

// ---------------- kernel: pre-round head_W to fp16 ---------------------------------
__global__ __launch_bounds__(256) void k_hwt(const float* __restrict__ hw)
{
    int idx = blockIdx.x*256 + threadIdx.x;
    if (idx < KT*Pp) g_HWh[idx] = __float2half_rn(hw[idx]);
}

// ---------------- persistent fused temporal MLP + gcn_W (fp16 wmma, 512 thr) -------
#define TG_SMEM ((Ss*WLH + Ss*XPH + Hh*XPH)*2 + (Ss*XP + Ss)*4)
__global__ __launch_bounds__(512) void k_tempgcn_mma(
    const float* __restrict__ W, const float* __restrict__ tb, const float* __restrict__ Wg)
{
    extern __shared__ char smc[];
    __half* WsmH = (__half*)smc;             // [192][WLH]
    __half* XsH  = WsmH + Ss*WLH;            // [192][XPH]
    __half* WgsH = XsH + Ss*XPH;             // [64][XPH]
    float*  Ys   = (float*)(WgsH + Hh*XPH);  // [192][XP]
    float*  tbs  = Ys + Ss*XP;               // [192]

    int tid = threadIdx.x;
    int wid = tid >> 5;
    int wt = wid >> 2;
    int wh = wid & 3;

    for (int i4 = tid; i4 < Ss*48; i4 += 512) {
        int t = i4 / 48, c4 = i4 % 48;
        float4 v = *(const float4*)(W + (size_t)t*Ss + c4*4);
        __half2* d = (__half2*)(WsmH + t*WLH + c4*4);
        d[0] = __floats2half2_rn(v.x, v.y);
        d[1] = __floats2half2_rn(v.z, v.w);
    }
    #pragma unroll
    for (int q = 0; q < 2; q++) {
        int i4 = tid + 512*q;
        int r = i4 >> 4, c4 = i4 & 15;
        float4 v = *(const float4*)(Wg + (size_t)r*Hh + c4*4);
        __half2* d = (__half2*)(WgsH + r*XPH + c4*4);
        d[0] = __floats2half2_rn(v.x, v.y);
        d[1] = __floats2half2_rn(v.z, v.w);
    }
    if (tid < Ss) tbs[tid] = tb[tid];

    for (int bn = blockIdx.x; bn < BN; bn += gridDim.x) {
        float* xg = g_X + (size_t)bn*SH;

        #pragma unroll
        for (int q = 0; q < 6; q++) {
            int i4 = tid + 512*q;
            int t = i4 >> 4, c4 = i4 & 15;
            float4 v = *(const float4*)(xg + (size_t)t*Hh + c4*4);
            __half2* d = (__half2*)(XsH + t*XPH + c4*4);
            d[0] = __floats2half2_rn(v.x, v.y);
            d[1] = __floats2half2_rn(v.z, v.w);
        }
        __syncthreads();

        wmma::fragment<wmma::accumulator,16,16,16,float> c[3];
        #pragma unroll
        for (int i = 0; i < 3; i++) wmma::fill_fragment(c[i], 0.f);

        #pragma unroll 4
        for (int k16 = 0; k16 < 12; k16++) {
            wmma::fragment<wmma::matrix_a,16,16,16,__half,wmma::row_major> a[3];
            wmma::fragment<wmma::matrix_b,16,16,16,__half,wmma::row_major> bf;
            #pragma unroll
            for (int i = 0; i < 3; i++)
                wmma::load_matrix_sync(a[i], WsmH + (wt*48 + i*16)*WLH + k16*16, WLH);
            wmma::load_matrix_sync(bf, XsH + k16*16*XPH + wh*16, XPH);
            #pragma unroll
            for (int i = 0; i < 3; i++)
                wmma::mma_sync(c[i], a[i], bf, c[i]);
        }
        __syncthreads();

        #pragma unroll
        for (int i = 0; i < 3; i++)
            wmma::store_matrix_sync(Ys + (wt*48 + i*16)*XP + wh*16,
                                    c[i], XP, wmma::mem_row_major);
        __syncthreads();

        #pragma unroll 8
        for (int q = 0; q < 24; q++) {
            int i = tid + 512*q;
            int t = i >> 6, h = i & 63;
            float y = Ys[t*XP + h] + tbs[t];
            float xn = xg[i] + gelu_exact(y);
            xg[i] = xn;
            XsH[t*XPH + h] = __float2half_rn(xn);
        }
        __syncthreads();

        // GEMM2: XW = x_new @ Wg (fp16) -> g_XWh
        #pragma unroll
        for (int i = 0; i < 3; i++) wmma::fill_fragment(c[i], 0.f);
        #pragma unroll
        for (int k16 = 0; k16 < 4; k16++) {
            wmma::fragment<wmma::matrix_a,16,16,16,__half,wmma::row_major> a[3];
            wmma::fragment<wmma::matrix_b,16,16,16,__half,wmma::row_major> bf;
            #pragma unroll
            for (int i = 0; i < 3; i++)
                wmma::load_matrix_sync(a[i], XsH + (wt*48 + i*16)*XPH + k16*16, XPH);
            wmma::load_matrix_sync(bf, WgsH + k16*16*XPH + wh*16, XPH);
            #pragma unroll
            for (int i = 0; i < 3; i++)
                wmma::mma_sync(c[i], a[i], bf, c[i]);
        }
        #pragma unroll
        for (int i = 0; i < 3; i++)
            wmma::store_matrix_sync(Ys + (wt*48 + i*16)*XP + wh*16,
                                    c[i], XP, wmma::mem_row_major);
        __syncthreads();
        __half* xwo = g_XWh + (size_t)bn*SH;
        #pragma unroll 4
        for (int q = 0; q < 12; q++) {
            int i = tid + 512*q;
            int t = i >> 5, hp = i & 31;
            float2 v = *(const float2*)(Ys + t*XP + hp*2);
            *(__half2*)(xwo + t*Hh + hp*2) = __floats2half2_rn(v.x, v.y);
        }
        __syncthreads();
    }
}

// ---------------- mixln fp16 (R15 shape): one s-block per CTA ----------------------
#define MM 128
#define ML_SMEM (MM*ALH*2 + MM*XP*4)
__global__ __launch_bounds__(256, 2) void k_mixln_mma(
    const float* __restrict__ gb, const float* __restrict__ lw, const float* __restrict__ lb,
    int last)
{
    extern __shared__ char smc[];
    __half* AsH = (__half*)smc;                 // [128][ALH]
    __half* BsH = (__half*)(smc + MM*ALH*2);    // [208][XPH] (union with Out)
    float*  Out = (float*) (smc + MM*ALH*2);    // [128][XP]

    int b = blockIdx.z, m0 = blockIdx.y*MM, sblk = blockIdx.x;
    int tid = threadIdx.x, wid = tid >> 5, lane = tid & 31;
    int wm = wid >> 1, whh = wid & 1;

    int wmax = (blockIdx.y == 0) ? 4 : 3;
    int rowcnt = wmax * 32;
    bool act = (wm < wmax);

    // stage A-slice [rowcnt][208]
    for (int i = tid; i < rowcnt*26; i += 256) {
        int row = i / 26, c8 = i % 26;
        cp16(AsH + row*ALH + c8*8, g_Ah + (size_t)(m0+row)*208 + c8*8);
    }
    // stage B [208][64]
    const __half* xwb = g_XWh + (size_t)b*Nn*SH + (size_t)sblk*Hh;
    for (int i = tid; i < 208*8; i += 256) {
        int n = i >> 3, c8 = i & 7;
        cp16(BsH + n*XPH + c8*8, xwb + (size_t)n*SH + c8*8);
    }
    cp_commit();
    cp_wait<0>();
    __syncthreads();

    wmma::fragment<wmma::accumulator,16,16,16,float> c[2][2];
    #pragma unroll
    for (int i = 0; i < 2; i++)
        #pragma unroll
        for (int j = 0; j < 2; j++) wmma::fill_fragment(c[i][j], 0.f);

    if (act) {
        #pragma unroll 1
        for (int k16 = 0; k16 < 13; k16++) {
            wmma::fragment<wmma::matrix_a,16,16,16,__half,wmma::row_major> a[2];
            wmma::fragment<wmma::matrix_b,16,16,16,__half,wmma::row_major> bf[2];
            #pragma unroll
            for (int i = 0; i < 2; i++)
                wmma::load_matrix_sync(a[i], AsH + (wm*32 + i*16)*ALH + k16*16, ALH);
            #pragma unroll
            for (int j = 0; j < 2; j++)
                wmma::load_matrix_sync(bf[j], BsH + k16*16*XPH + whh*32 + j*16, XPH);
            #pragma unroll
            for (int i = 0; i < 2; i++)
                #pragma unroll
                for (int j = 0; j < 2; j++)
                    wmma::mma_sync(c[i][j], a[i], bf[j], c[i][j]);
        }
    }
    __syncthreads();   // BsH reads done; Out overwrites union

    if (act) {
        #pragma unroll
        for (int i = 0; i < 2; i++)
            #pragma unroll
            for (int j = 0; j < 2; j++)
                wmma::store_matrix_sync(Out + (wm*32 + i*16)*XP + whh*32 + j*16,
                                        c[i][j], XP, wmma::mem_row_major);
    }
    __syncthreads();

    float gb0 = gb[lane],    gb1 = gb[lane+32];
    float lw0 = lw[lane],    lw1 = lw[lane+32];
    float lb0 = lb[lane],    lb1 = lb[lane+32];
    #pragma unroll
    for (int it = 0; it < 16; it++) {
        int r = wid*16 + it;
        int m = m0 + r;
        if (m >= Nn) break;
        size_t xi = ((size_t)(b*Nn + m)*Ss + sblk)*Hh + lane;
        float v0 = g_X[xi]      + Out[r*XP + lane]      + gb0;
        float v1 = g_X[xi + 32] + Out[r*XP + lane + 32] + gb1;
        float s = v0 + v1, q = v0*v0 + v1*v1;
        #pragma unroll
        for (int o = 16; o > 0; o >>= 1) {
            s += __shfl_xor_sync(0xffffffffu, s, o);
            q += __shfl_xor_sync(0xffffffffu, q, o);
        }
        float mu = s*(1.f/Hh), var = q*(1.f/Hh) - mu*mu;
        float rinv = rsqrtf(var + 1e-5f);
        float o0 = (v0-mu)*rinv*lw0 + lb0;
        float o1 = (v1-mu)*rinv*lw1 + lb1;
        g_X[xi]      = o0;
        g_X[xi + 32] = o1;
        if (last) {
            g_Xhd[xi]      = __float2half_rn(o0);
            g_Xhd[xi + 32] = __float2half_rn(o1);
        }
    }
}

// ---------------- kernel: future projection (fp16 output) --------------------------
__global__ __launch_bounds__(256) void k_futr(
    const float* __restrict__ xf, const float* __restrict__ fw, const float* __restrict__ fb)
{
    int idx = blockIdx.x*blockDim.x + threadIdx.x;
    const int tot = BN*Pp*Hh;
    if (idx >= tot) return;
    int h = idx & 63;
    int p = (idx >> 6) % Pp;
    int bn = idx / (Pp*Hh);
    const float* xr = xf + ((size_t)bn*Pp + p)*FNn;
    float acc = fb[h];
    #pragma unroll
    for (int f = 0; f < FNn; f++) acc += xr[f]*fw[f*Hh+h];
    g_XFh[idx] = __float2half_rn(acc);
}

// ---------------- head GEMM, fp16 wmma split-K, cp.async double-buffer -------------
#define HD_SMEM ((128*FH + 64*WHH)*2*2)
__global__ __launch_bounds__(256) void k_head_mma()
{
    extern __shared__ char smhc[];
    __half* F0 = (__half*)smhc;
    __half* W0 = F0 + 128*FH;
    __half* F1 = W0 + 64*WHH;
    __half* W1 = F1 + 128*FH;

    int m0 = blockIdx.x*128;
    int k0 = blockIdx.y*(KT/8);      // 1920 per split, 30 chunks of 64
    int tid = threadIdx.x, wid = tid >> 5;

    wmma::fragment<wmma::accumulator,16,16,16,float> c[3];
    #pragma unroll
    for (int j = 0; j < 3; j++) wmma::fill_fragment(c[j], 0.f);

    {
        int kc = k0;
        #pragma unroll
        for (int q = 0; q < 4; q++) {
            int i8 = tid + 256*q;
            int row = i8 >> 3, cc = i8 & 7;
            int k = kc + cc*8;
            const __half* src = (k < SH) ? (g_Xhd + (size_t)(m0+row)*SH + k)
                                         : (g_XFh + (size_t)(m0+row)*(Pp*Hh) + (k - SH));
            cp16(F0 + row*FH + cc*8, src);
        }
        for (int i8 = tid; i8 < 64*6; i8 += 256) {
            int row = i8 / 6, cc = i8 % 6;
            cp16(W0 + row*WHH + cc*8, g_HWh + (size_t)(kc+row)*Pp + cc*8);
        }
        cp_commit();
    }

    for (int ch = 0; ch < 30; ch++) {
        __half* Fb = (ch & 1) ? F1 : F0;
        __half* Wb = (ch & 1) ? W1 : W0;
        if (ch < 29) {
            int kc = k0 + (ch+1)*64;
            __half* Fn = ((ch+1) & 1) ? F1 : F0;
            __half* Wn = ((ch+1) & 1) ? W1 : W0;
            #pragma unroll
            for (int q = 0; q < 4; q++) {
                int i8 = tid + 256*q;
                int row = i8 >> 3, cc = i8 & 7;
                int k = kc + cc*8;
                const __half* src = (k < SH) ? (g_Xhd + (size_t)(m0+row)*SH + k)
                                             : (g_XFh + (size_t)(m0+row)*(Pp*Hh) + (k - SH));
                cp16(Fn + row*FH + cc*8, src);
            }
            for (int i8 = tid; i8 < 64*6; i8 += 256) {
                int row = i8 / 6, cc = i8 % 6;
                cp16(Wn + row*WHH + cc*8, g_HWh + (size_t)(kc+row)*Pp + cc*8);
            }
            cp_commit();
            cp_wait<1>();
        } else {
            cp_wait<0>();
        }
        __syncthreads();

        #pragma unroll
        for (int k16 = 0; k16 < 4; k16++) {
            wmma::fragment<wmma::matrix_a,16,16,16,__half,wmma::row_major> a;
            wmma::load_matrix_sync(a, Fb + wid*16*FH + k16*16, FH);
            #pragma unroll
            for (int j = 0; j < 3; j++) {
                wmma::fragment<wmma::matrix_b,16,16,16,__half,wmma::row_major> bf;
                wmma::load_matrix_sync(bf, Wb + k16*16*WHH + j*16, WHH);
                wmma::mma_sync(c[j], a, bf, c[j]);
            }
        }
        __syncthreads();
    }
    float* hp = g_HP + (size_t)blockIdx.y*BN*Pp + (size_t)(m0 + wid*16)*Pp;
    #pragma unroll
    for (int j = 0; j < 3; j++)
        wmma::store_matrix_sync(hp + j*16, c[j], Pp, wmma::mem_row_major);
}

__global__ __launch_bounds__(256) void k_head_red(
    const float* __restrict__ hb, float* __restrict__ out)
{
    int idx = blockIdx.x*256 + threadIdx.x;
    if (idx >= BN*Pp) return;
    int p = idx % Pp;
    float acc = hb[p];
    #pragma unroll
    for (int z = 0; z < 8; z++) acc += g_HP[(size_t)z*BN*Pp + idx];
    out[idx] = acc;
}

// ---------------- launcher ---------------------------------------------------------
extern "C" void kernel_launch(void* const* d_in, const int* in_sizes, int n_in,
                              void* d_out, int out_size)
{
    const float* x        = (const float*)d_in[0];
    const float* x_future = (const float*)d_in[1];
    const float* adj      = (const float*)d_in[2];
    const float* node_emb = (const float*)d_in[3];
    const float* galpha   = (const float*)d_in[4];
    const float* in_w     = (const float*)d_in[5];
    const float* in_b     = (const float*)d_in[6];
    const float* proj_W   = (const float*)d_in[7];
    const float* proj_b   = (const float*)d_in[8];
    const float* temp_W   = (const float*)d_in[9];
    const float* temp_b   = (const float*)d_in[10];
    const float* gcn_W    = (const float*)d_in[11];
    const float* gcn_b    = (const float*)d_in[12];
    const float* ln_w     = (const float*)d_in[13];
    const float* ln_b     = (const float*)d_in[14];
    const float* futr_W   = (const float*)d_in[15];
    const float* futr_b   = (const float*)d_in[16];
    const float* head_W   = (const float*)d_in[17];
    const float* head_b   = (const float*)d_in[18];
    float* out = (float*)d_out;

    static bool attr_set = false;
    if (!attr_set) {
        cudaFuncSetAttribute(k_tempgcn_mma, cudaFuncAttributeMaxDynamicSharedMemorySize, TG_SMEM);
        cudaFuncSetAttribute(k_mixln_mma,   cudaFuncAttributeMaxDynamicSharedMemorySize, ML_SMEM);
        cudaFuncSetAttribute(k_head_mma,    cudaFuncAttributeMaxDynamicSharedMemorySize, HD_SMEM);
        attr_set = true;
    }

    // launch order: my #4 = first mixln (profiled by ncu)
    k_innorm_proj<<<BN, 256>>>(x, in_w, in_b, proj_W, proj_b, node_emb);      // 1
    k_adj<<<1, 256>>>(adj, node_emb, galpha);                                  // 2
    for (int i = 0; i < NBb; i++) {
        k_tempgcn_mma<<<148, 512, TG_SMEM>>>(temp_W + (size_t)i*Ss*Ss,         // 3,5,7
                                             temp_b + (size_t)i*Ss,
                                             gcn_W + (size_t)i*Hh*Hh);
        k_mixln_mma<<<dim3(Ss, 2, Bb), 256, ML_SMEM>>>(gcn_b + (size_t)i*Hh,   // 4 <- profiled
                                                       ln_w + (size_t)i*Hh, ln_b + (size_t)i*Hh,
                                                       (i == NBb-1) ? 1 : 0);
    }
    {
        const int tot = BN*Pp*Hh;
        k_futr<<<(tot + 255)/256, 256>>>(x_future, futr_W, futr_b);
    }
    k_hwt<<<(KT*Pp + 255)/256, 256>>>(head_W);
    k_head_mma<<<dim3(50, 8), 256, HD_SMEM>>>();
    k_head_red<<<(BN*Pp + 255)/256, 256>>>(head_b, out);
}